// round 15
// baseline (speedup 1.0000x reference)
#include <cuda_runtime.h>
#include <cuda_bf16.h>

// Fixed problem shapes
#define NBOX 256
#define UH   200
#define UW   304
#define H1   100
#define W1   152
#define H2   50
#define W2   76
#define P0   (UH * UW)   // 60800
#define P1   (H1 * W1)   // 15200
#define P2   (H2 * W2)   //  3800

// NHWC scratch: [P][256] per level, plus NHWC output staging [n][lvl][cell][256]
__device__ float g_nhwc0[P0 * 256];
__device__ float g_nhwc1[P1 * 256];
__device__ float g_nhwc2[P2 * 256];
__device__ float g_outs[NBOX * 3 * 49 * 256];

// ---------------------------------------------------------------------------
// K1: [256][P] -> [P][256] tiled transpose
// ---------------------------------------------------------------------------
__global__ void __launch_bounds__(256)
transpose_kernel(const float* __restrict__ src, float* __restrict__ dst, int P)
{
    __shared__ float tile[32][33];
    const int p0 = blockIdx.x * 32;
    const int c0 = blockIdx.y * 32;
    const int tx = threadIdx.x, ty = threadIdx.y;
    #pragma unroll
    for (int j = 0; j < 4; j++) {
        int p = p0 + tx;
        if (p < P) tile[ty + j * 8][tx] = src[(c0 + ty + j * 8) * P + p];
    }
    __syncthreads();
    #pragma unroll
    for (int j = 0; j < 4; j++) {
        int p = p0 + ty + j * 8;
        if (p < P) dst[p * 256 + (c0 + tx)] = tile[tx][ty + j * 8];
    }
}

// ---------------------------------------------------------------------------
// Coarse tap builder (composed upsample+roialign bilinear), either axis.
// ---------------------------------------------------------------------------
__device__ __forceinline__ void coarse_taps(int lvl, int axis, int p,
                                            float b1, float bt,
                                            int* ci, float* cw, int& mn, int& mx)
{
    const float inv   = (lvl == 1) ? 0.5f : 0.25f;
    const int   cdim  = axis ? ((lvl == 1) ? H1 : H2) : ((lvl == 1) ? W1 : W2);
    const int   updim = axis ? UH : UW;
    mn = 1 << 30; mx = -1;
    int e = 0;
    #pragma unroll
    for (int s = 0; s < 2; s++) {
        float T  = b1 + ((float)p + 0.25f + 0.5f * (float)s) * bt;
        float Tc = fminf(fmaxf(T, 0.0f), (float)(updim - 1));
        int   u0 = (int)Tc;
        int   u1 = min(u0 + 1, updim - 1);
        float fu = Tc - (float)u0;
        #pragma unroll
        for (int b = 0; b < 2; b++) {
            int   u  = b ? u1 : u0;
            float wu = b ? (0.5f * fu) : (0.5f * (1.0f - fu));
            float g  = ((float)u + 0.5f) * inv - 0.5f;
            g = fminf(fmaxf(g, 0.0f), (float)(cdim - 1));
            int   c0 = (int)g;
            int   c1 = min(c0 + 1, cdim - 1);
            float fc = g - (float)c0;
            ci[e] = c0; cw[e] = wu * (1.0f - fc); e++;
            ci[e] = c1; cw[e] = wu * fc;          e++;
            mn = min(mn, c0); mx = max(mx, c1);
        }
    }
}

// ---------------------------------------------------------------------------
// K2 coarse body: warp per cell, lanes = channels (float4), RYxRX dense taps.
// ---------------------------------------------------------------------------
template<int RY, int RX>
__device__ __forceinline__ void coarse_cells_nhwc(
    const float* __restrict__ plane, int W_,
    const float (*s_cw)[7][5], const int (*s_cb)[7],
    int wid, int lane, float* __restrict__ outbase)
{
    for (int cell = wid; cell < 49; cell += 8) {
        const int oh = cell / 7, ow = cell % 7;
        float wy[RY], wx[RX];
        #pragma unroll
        for (int r = 0; r < RY; r++) wy[r] = s_cw[1][oh][r];
        #pragma unroll
        for (int r = 0; r < RX; r++) wx[r] = s_cw[0][ow][r];
        const float* q = plane + (s_cb[1][oh] * W_ + s_cb[0][ow]) * 256 + lane * 4;
        float* oc = outbase + cell * 256 + lane * 4;
        #pragma unroll
        for (int chunk = 0; chunk < 2; chunk++) {
            float4 acc = make_float4(0.f, 0.f, 0.f, 0.f);
            #pragma unroll
            for (int ry = 0; ry < RY; ry++) {
                float4 sx = make_float4(0.f, 0.f, 0.f, 0.f);
                #pragma unroll
                for (int rx = 0; rx < RX; rx++) {
                    float4 v = __ldg((const float4*)(q + chunk * 128 + (ry * W_ + rx) * 256));
                    sx.x = fmaf(wx[rx], v.x, sx.x);
                    sx.y = fmaf(wx[rx], v.y, sx.y);
                    sx.z = fmaf(wx[rx], v.z, sx.z);
                    sx.w = fmaf(wx[rx], v.w, sx.w);
                }
                acc.x = fmaf(wy[ry], sx.x, acc.x);
                acc.y = fmaf(wy[ry], sx.y, acc.y);
                acc.z = fmaf(wy[ry], sx.z, acc.z);
                acc.w = fmaf(wy[ry], sx.w, acc.w);
            }
            *((float4*)(oc + chunk * 128)) = acc;
        }
    }
}

template<int RY>
__device__ __forceinline__ void dispatch_rx(int rNx,
    const float* __restrict__ plane, int W_,
    const float (*s_cw)[7][5], const int (*s_cb)[7],
    int wid, int lane, float* __restrict__ outbase)
{
    switch (rNx) {
        case 1: coarse_cells_nhwc<RY,1>(plane, W_, s_cw, s_cb, wid, lane, outbase); break;
        case 2: coarse_cells_nhwc<RY,2>(plane, W_, s_cw, s_cb, wid, lane, outbase); break;
        case 3: coarse_cells_nhwc<RY,3>(plane, W_, s_cw, s_cb, wid, lane, outbase); break;
        case 4: coarse_cells_nhwc<RY,4>(plane, W_, s_cw, s_cb, wid, lane, outbase); break;
        default: coarse_cells_nhwc<RY,5>(plane, W_, s_cw, s_cb, wid, lane, outbase); break;
    }
}

// ---------------------------------------------------------------------------
// K2: fused RoIAlign on NHWC maps. grid (256 boxes, 3 levels), 256 threads.
// ---------------------------------------------------------------------------
__global__ void __launch_bounds__(256)
roialign_nhwc_kernel(const float* __restrict__ boxes)
{
    const int n   = blockIdx.x;
    const int lvl = blockIdx.y;
    const int tid = threadIdx.x;

    __shared__ float s_w0[2][7][4];
    __shared__ int   s_i0[2][7][4];
    __shared__ float s_cw[2][7][5];
    __shared__ int   s_cb[2][7];
    __shared__ int   s_mn[2][7], s_mx[2][7];
    __shared__ int   s_rN[2];

    // ---- phase A ----
    if (tid < 14) {
        const int axis = tid / 7;
        const int p    = tid % 7;
        float b1 = boxes[n * 4 + axis]     * 0.25f;
        float b2 = boxes[n * 4 + 2 + axis] * 0.25f;
        float bt = fmaxf(b2 - b1, 1.0f) * (1.0f / 7.0f);
        const int updim = axis ? UH : UW;

        if (lvl == 0) {
            #pragma unroll
            for (int s = 0; s < 2; s++) {
                float T  = b1 + ((float)p + 0.25f + 0.5f * (float)s) * bt;
                float Tc = fminf(fmaxf(T, 0.0f), (float)(updim - 1));
                int   i0 = (int)Tc;
                int   i1 = min(i0 + 1, updim - 1);
                float f  = Tc - (float)i0;
                s_i0[axis][p][2 * s + 0] = i0;
                s_i0[axis][p][2 * s + 1] = i1;
                s_w0[axis][p][2 * s + 0] = 0.5f * (1.0f - f);
                s_w0[axis][p][2 * s + 1] = 0.5f * f;
            }
        } else {
            int ci[8]; float cw[8]; int mn, mx;
            coarse_taps(lvl, axis, p, b1, bt, ci, cw, mn, mx);
            s_mn[axis][p] = mn;
            s_mx[axis][p] = mx;
        }
    }
    __syncthreads();

    if (lvl != 0 && tid < 2) {
        int r = 1;
        #pragma unroll
        for (int k = 0; k < 7; k++) r = max(r, s_mx[tid][k] - s_mn[tid][k] + 1);
        s_rN[tid] = min(r, 5);
    }
    __syncthreads();

    // ---- phase B: bin taps into windows anchored with the known rN ----
    if (lvl != 0 && tid < 14) {
        const int axis = tid / 7;
        const int p    = tid % 7;
        const int cdim = axis ? ((lvl == 1) ? H1 : H2) : ((lvl == 1) ? W1 : W2);
        const int rN   = s_rN[axis];
        float b1 = boxes[n * 4 + axis]     * 0.25f;
        float b2 = boxes[n * 4 + 2 + axis] * 0.25f;
        float bt = fmaxf(b2 - b1, 1.0f) * (1.0f / 7.0f);

        int ci[8]; float cw[8]; int mn, mx;
        coarse_taps(lvl, axis, p, b1, bt, ci, cw, mn, mx);

        int wb = min(mn, cdim - rN);
        float w[5] = {0, 0, 0, 0, 0};
        #pragma unroll
        for (int k = 0; k < 8; k++) {
            int off = min(max(ci[k] - wb, 0), rN - 1);
            w[off] += cw[k];
        }
        s_cb[axis][p] = wb;
        #pragma unroll
        for (int k = 0; k < 5; k++) s_cw[axis][p][k] = w[k];
    }
    __syncthreads();

    // ---- main: warp per cell, lanes = channel float4 ----
    const int wid  = tid >> 5;
    const int lane = tid & 31;
    float* outbase = g_outs + (size_t)(n * 3 + lvl) * 49 * 256;

    if (lvl == 0) {
        for (int cell = wid; cell < 49; cell += 8) {
            const int oh = cell / 7, ow = cell % 7;
            int   offy[4], offx[4];
            float wy[4],  wx[4];
            #pragma unroll
            for (int t = 0; t < 4; t++) {
                offy[t] = s_i0[1][oh][t] * UW;
                wy[t]   = s_w0[1][oh][t];
                offx[t] = s_i0[0][ow][t];
                wx[t]   = s_w0[0][ow][t];
            }
            const float* q = g_nhwc0 + lane * 4;
            float* oc = outbase + cell * 256 + lane * 4;
            #pragma unroll
            for (int chunk = 0; chunk < 2; chunk++) {
                float4 acc = make_float4(0.f, 0.f, 0.f, 0.f);
                #pragma unroll
                for (int ty = 0; ty < 4; ty++) {
                    float4 sx = make_float4(0.f, 0.f, 0.f, 0.f);
                    #pragma unroll
                    for (int tx = 0; tx < 4; tx++) {
                        float4 v = __ldg((const float4*)(q + chunk * 128 + (offy[ty] + offx[tx]) * 256));
                        sx.x = fmaf(wx[tx], v.x, sx.x);
                        sx.y = fmaf(wx[tx], v.y, sx.y);
                        sx.z = fmaf(wx[tx], v.z, sx.z);
                        sx.w = fmaf(wx[tx], v.w, sx.w);
                    }
                    acc.x = fmaf(wy[ty], sx.x, acc.x);
                    acc.y = fmaf(wy[ty], sx.y, acc.y);
                    acc.z = fmaf(wy[ty], sx.z, acc.z);
                    acc.w = fmaf(wy[ty], sx.w, acc.w);
                }
                *((float4*)(oc + chunk * 128)) = acc;
            }
        }
    } else {
        const float* plane = (lvl == 1) ? g_nhwc1 : g_nhwc2;
        const int W_ = (lvl == 1) ? W1 : W2;
        const int rNy = s_rN[1];
        const int rNx = s_rN[0];
        switch (rNy) {
            case 1: dispatch_rx<1>(rNx, plane, W_, s_cw, s_cb, wid, lane, outbase); break;
            case 2: dispatch_rx<2>(rNx, plane, W_, s_cw, s_cb, wid, lane, outbase); break;
            case 3: dispatch_rx<3>(rNx, plane, W_, s_cw, s_cb, wid, lane, outbase); break;
            case 4: dispatch_rx<4>(rNx, plane, W_, s_cw, s_cb, wid, lane, outbase); break;
            default: dispatch_rx<5>(rNx, plane, W_, s_cw, s_cb, wid, lane, outbase); break;
        }
    }
}

// ---------------------------------------------------------------------------
// K3: per (box,lvl): [49][256] -> [256][49] into the final output.
// ---------------------------------------------------------------------------
__global__ void __launch_bounds__(256)
out_transpose_kernel(float* __restrict__ out)
{
    __shared__ float t[128][49];
    const int b    = blockIdx.x;          // n*3 + lvl
    const int tid  = threadIdx.x;
    const int wid  = tid >> 5;
    const int lane = tid & 31;
    const float* src = g_outs + (size_t)b * 49 * 256;
    const int n   = b / 3;
    const int lvl = b - n * 3;
    float* dst = out + (size_t)(n * 768 + lvl * 256) * 49;

    #pragma unroll
    for (int half = 0; half < 2; half++) {
        for (int i = tid; i < 49 * 128; i += 256) {
            int cell = i >> 7;
            int ch   = i & 127;
            t[ch][cell] = src[cell * 256 + half * 128 + ch];
        }
        __syncthreads();
        for (int r = wid; r < 128; r += 8) {
            float* drow = dst + (half * 128 + r) * 49;
            drow[lane] = t[r][lane];
            if (lane < 17) drow[32 + lane] = t[r][32 + lane];
        }
        __syncthreads();
    }
}

extern "C" void kernel_launch(void* const* d_in, const int* in_sizes, int n_in,
                              void* d_out, int out_size) {
    const float* feat0 = (const float*)d_in[0];
    const float* feat1 = (const float*)d_in[1];
    const float* feat2 = (const float*)d_in[2];
    const float* boxes = (const float*)d_in[3];
    float* out = (float*)d_out;

    float* p0; cudaGetSymbolAddress((void**)&p0, g_nhwc0);
    float* p1; cudaGetSymbolAddress((void**)&p1, g_nhwc1);
    float* p2; cudaGetSymbolAddress((void**)&p2, g_nhwc2);

    dim3 tb(32, 8);
    transpose_kernel<<<dim3((P0 + 31) / 32, 8), tb>>>(feat0, p0, P0);
    transpose_kernel<<<dim3((P1 + 31) / 32, 8), tb>>>(feat1, p1, P1);
    transpose_kernel<<<dim3((P2 + 31) / 32, 8), tb>>>(feat2, p2, P2);

    roialign_nhwc_kernel<<<dim3(NBOX, 3), 256>>>(boxes);

    out_transpose_kernel<<<NBOX * 3, 256>>>(out);
}

// round 16
// speedup vs baseline: 1.1028x; 1.1028x over previous
#include <cuda_runtime.h>
#include <cuda_bf16.h>

// Fixed problem shapes
#define NBOX 256
#define UH   200
#define UW   304
#define H1   100
#define W1   152
#define H2   50
#define W2   76
#define P0   (UH * UW)   // 60800
#define P1   (H1 * W1)   // 15200
#define P2   (H2 * W2)   //  3800

#define NB0  ((P0 + 31) / 32)   // 1900
#define NB1  ((P1 + 31) / 32)   // 475
#define NB2  ((P2 + 31) / 32)   // 119

// NHWC scratch: [P][256] per level
__device__ float g_nhwc0[P0 * 256];
__device__ float g_nhwc1[P1 * 256];
__device__ float g_nhwc2[P2 * 256];

// ---------------------------------------------------------------------------
// K1: all three [256][P] -> [P][256] transposes in one launch.
// ---------------------------------------------------------------------------
__global__ void __launch_bounds__(256)
transpose_all_kernel(const float* __restrict__ feat0,
                     const float* __restrict__ feat1,
                     const float* __restrict__ feat2)
{
    __shared__ float tile[32][33];
    int bx = blockIdx.x;
    const float* src;
    float* dst;
    int P;
    if (bx < NB0)            { src = feat0; dst = g_nhwc0; P = P0; }
    else if (bx < NB0 + NB1) { src = feat1; dst = g_nhwc1; P = P1; bx -= NB0; }
    else                     { src = feat2; dst = g_nhwc2; P = P2; bx -= NB0 + NB1; }

    const int p0 = bx * 32;
    const int c0 = blockIdx.y * 32;
    const int tx = threadIdx.x, ty = threadIdx.y;
    #pragma unroll
    for (int j = 0; j < 4; j++) {
        int p = p0 + tx;
        if (p < P) tile[ty + j * 8][tx] = src[(c0 + ty + j * 8) * P + p];
    }
    __syncthreads();
    #pragma unroll
    for (int j = 0; j < 4; j++) {
        int p = p0 + ty + j * 8;
        if (p < P) dst[p * 256 + (c0 + tx)] = tile[tx][ty + j * 8];
    }
}

// ---------------------------------------------------------------------------
// Coarse tap builder (composed upsample+roialign bilinear), either axis.
// ---------------------------------------------------------------------------
__device__ __forceinline__ void coarse_taps(int lvl, int axis, int p,
                                            float b1, float bt,
                                            int* ci, float* cw, int& mn, int& mx)
{
    const float inv   = (lvl == 1) ? 0.5f : 0.25f;
    const int   cdim  = axis ? ((lvl == 1) ? H1 : H2) : ((lvl == 1) ? W1 : W2);
    const int   updim = axis ? UH : UW;
    mn = 1 << 30; mx = -1;
    int e = 0;
    #pragma unroll
    for (int s = 0; s < 2; s++) {
        float T  = b1 + ((float)p + 0.25f + 0.5f * (float)s) * bt;
        float Tc = fminf(fmaxf(T, 0.0f), (float)(updim - 1));
        int   u0 = (int)Tc;
        int   u1 = min(u0 + 1, updim - 1);
        float fu = Tc - (float)u0;
        #pragma unroll
        for (int b = 0; b < 2; b++) {
            int   u  = b ? u1 : u0;
            float wu = b ? (0.5f * fu) : (0.5f * (1.0f - fu));
            float g  = ((float)u + 0.5f) * inv - 0.5f;
            g = fminf(fmaxf(g, 0.0f), (float)(cdim - 1));
            int   c0 = (int)g;
            int   c1 = min(c0 + 1, cdim - 1);
            float fc = g - (float)c0;
            ci[e] = c0; cw[e] = wu * (1.0f - fc); e++;
            ci[e] = c1; cw[e] = wu * fc;          e++;
            mn = min(mn, c0); mx = max(mx, c1);
        }
    }
}

// ---------------------------------------------------------------------------
// K2 coarse body for one channel-chunk: warp per cell, lanes = channel float4.
// Results go to smem staging tile s_t[ch][cell] (ch relative to chunk).
// ---------------------------------------------------------------------------
template<int RY, int RX>
__device__ __forceinline__ void coarse_cells_chunk(
    const float* __restrict__ plane, int W_, int chunk,
    const float (*s_cw)[7][5], const int (*s_cb)[7],
    int wid, int lane, float* __restrict__ s_t)
{
    for (int cell = wid; cell < 49; cell += 8) {
        const int oh = cell / 7, ow = cell % 7;
        float wy[RY], wx[RX];
        #pragma unroll
        for (int r = 0; r < RY; r++) wy[r] = s_cw[1][oh][r];
        #pragma unroll
        for (int r = 0; r < RX; r++) wx[r] = s_cw[0][ow][r];
        const float* q = plane + (s_cb[1][oh] * W_ + s_cb[0][ow]) * 256
                       + chunk * 128 + lane * 4;
        float4 acc = make_float4(0.f, 0.f, 0.f, 0.f);
        #pragma unroll
        for (int ry = 0; ry < RY; ry++) {
            float4 sx = make_float4(0.f, 0.f, 0.f, 0.f);
            #pragma unroll
            for (int rx = 0; rx < RX; rx++) {
                float4 v = __ldg((const float4*)(q + (ry * W_ + rx) * 256));
                sx.x = fmaf(wx[rx], v.x, sx.x);
                sx.y = fmaf(wx[rx], v.y, sx.y);
                sx.z = fmaf(wx[rx], v.z, sx.z);
                sx.w = fmaf(wx[rx], v.w, sx.w);
            }
            acc.x = fmaf(wy[ry], sx.x, acc.x);
            acc.y = fmaf(wy[ry], sx.y, acc.y);
            acc.z = fmaf(wy[ry], sx.z, acc.z);
            acc.w = fmaf(wy[ry], sx.w, acc.w);
        }
        s_t[(lane * 4 + 0) * 49 + cell] = acc.x;
        s_t[(lane * 4 + 1) * 49 + cell] = acc.y;
        s_t[(lane * 4 + 2) * 49 + cell] = acc.z;
        s_t[(lane * 4 + 3) * 49 + cell] = acc.w;
    }
}

template<int RY>
__device__ __forceinline__ void dispatch_rx(int rNx,
    const float* __restrict__ plane, int W_, int chunk,
    const float (*s_cw)[7][5], const int (*s_cb)[7],
    int wid, int lane, float* __restrict__ s_t)
{
    switch (rNx) {
        case 1: coarse_cells_chunk<RY,1>(plane, W_, chunk, s_cw, s_cb, wid, lane, s_t); break;
        case 2: coarse_cells_chunk<RY,2>(plane, W_, chunk, s_cw, s_cb, wid, lane, s_t); break;
        case 3: coarse_cells_chunk<RY,3>(plane, W_, chunk, s_cw, s_cb, wid, lane, s_t); break;
        case 4: coarse_cells_chunk<RY,4>(plane, W_, chunk, s_cw, s_cb, wid, lane, s_t); break;
        default: coarse_cells_chunk<RY,5>(plane, W_, chunk, s_cw, s_cb, wid, lane, s_t); break;
    }
}

// ---------------------------------------------------------------------------
// K2: fused RoIAlign on NHWC maps + direct NCHW output.
// grid (256 boxes, 3 levels), 256 threads. Two channel-chunks of 128.
// ---------------------------------------------------------------------------
__global__ void __launch_bounds__(256)
roialign_nhwc_kernel(const float* __restrict__ boxes, float* __restrict__ out)
{
    const int n   = blockIdx.x;
    const int lvl = blockIdx.y;
    const int tid = threadIdx.x;

    __shared__ float s_t[128 * 49];         // [ch_rel][cell] staging, 25 KB
    __shared__ float s_w0[2][7][4];
    __shared__ int   s_i0[2][7][4];
    __shared__ float s_cw[2][7][5];
    __shared__ int   s_cb[2][7];
    __shared__ int   s_mn[2][7], s_mx[2][7];
    __shared__ int   s_rN[2];

    // ---- phase A ----
    if (tid < 14) {
        const int axis = tid / 7;
        const int p    = tid % 7;
        float b1 = boxes[n * 4 + axis]     * 0.25f;
        float b2 = boxes[n * 4 + 2 + axis] * 0.25f;
        float bt = fmaxf(b2 - b1, 1.0f) * (1.0f / 7.0f);
        const int updim = axis ? UH : UW;

        if (lvl == 0) {
            #pragma unroll
            for (int s = 0; s < 2; s++) {
                float T  = b1 + ((float)p + 0.25f + 0.5f * (float)s) * bt;
                float Tc = fminf(fmaxf(T, 0.0f), (float)(updim - 1));
                int   i0 = (int)Tc;
                int   i1 = min(i0 + 1, updim - 1);
                float f  = Tc - (float)i0;
                s_i0[axis][p][2 * s + 0] = i0;
                s_i0[axis][p][2 * s + 1] = i1;
                s_w0[axis][p][2 * s + 0] = 0.5f * (1.0f - f);
                s_w0[axis][p][2 * s + 1] = 0.5f * f;
            }
        } else {
            int ci[8]; float cw[8]; int mn, mx;
            coarse_taps(lvl, axis, p, b1, bt, ci, cw, mn, mx);
            s_mn[axis][p] = mn;
            s_mx[axis][p] = mx;
        }
    }
    __syncthreads();

    if (lvl != 0 && tid < 2) {
        int r = 1;
        #pragma unroll
        for (int k = 0; k < 7; k++) r = max(r, s_mx[tid][k] - s_mn[tid][k] + 1);
        s_rN[tid] = min(r, 5);
    }
    __syncthreads();

    // ---- phase B: bin taps into windows anchored with the known rN ----
    if (lvl != 0 && tid < 14) {
        const int axis = tid / 7;
        const int p    = tid % 7;
        const int cdim = axis ? ((lvl == 1) ? H1 : H2) : ((lvl == 1) ? W1 : W2);
        const int rN   = s_rN[axis];
        float b1 = boxes[n * 4 + axis]     * 0.25f;
        float b2 = boxes[n * 4 + 2 + axis] * 0.25f;
        float bt = fmaxf(b2 - b1, 1.0f) * (1.0f / 7.0f);

        int ci[8]; float cw[8]; int mn, mx;
        coarse_taps(lvl, axis, p, b1, bt, ci, cw, mn, mx);

        int wb = min(mn, cdim - rN);
        float w[5] = {0, 0, 0, 0, 0};
        #pragma unroll
        for (int k = 0; k < 8; k++) {
            int off = min(max(ci[k] - wb, 0), rN - 1);
            w[off] += cw[k];
        }
        s_cb[axis][p] = wb;
        #pragma unroll
        for (int k = 0; k < 5; k++) s_cw[axis][p][k] = w[k];
    }
    __syncthreads();

    // ---- main: two channel-chunks, each computed to smem then written NCHW --
    const int wid  = tid >> 5;
    const int lane = tid & 31;
    float* outd = out + (size_t)(n * 768 + lvl * 256) * 49;

    #pragma unroll
    for (int chunk = 0; chunk < 2; chunk++) {
        if (lvl == 0) {
            for (int cell = wid; cell < 49; cell += 8) {
                const int oh = cell / 7, ow = cell % 7;
                int   offy[4], offx[4];
                float wy[4],  wx[4];
                #pragma unroll
                for (int t = 0; t < 4; t++) {
                    offy[t] = s_i0[1][oh][t] * UW;
                    wy[t]   = s_w0[1][oh][t];
                    offx[t] = s_i0[0][ow][t];
                    wx[t]   = s_w0[0][ow][t];
                }
                const float* q = g_nhwc0 + chunk * 128 + lane * 4;
                float4 acc = make_float4(0.f, 0.f, 0.f, 0.f);
                #pragma unroll
                for (int ty = 0; ty < 4; ty++) {
                    float4 sx = make_float4(0.f, 0.f, 0.f, 0.f);
                    #pragma unroll
                    for (int tx = 0; tx < 4; tx++) {
                        float4 v = __ldg((const float4*)(q + (offy[ty] + offx[tx]) * 256));
                        sx.x = fmaf(wx[tx], v.x, sx.x);
                        sx.y = fmaf(wx[tx], v.y, sx.y);
                        sx.z = fmaf(wx[tx], v.z, sx.z);
                        sx.w = fmaf(wx[tx], v.w, sx.w);
                    }
                    acc.x = fmaf(wy[ty], sx.x, acc.x);
                    acc.y = fmaf(wy[ty], sx.y, acc.y);
                    acc.z = fmaf(wy[ty], sx.z, acc.z);
                    acc.w = fmaf(wy[ty], sx.w, acc.w);
                }
                s_t[(lane * 4 + 0) * 49 + cell] = acc.x;
                s_t[(lane * 4 + 1) * 49 + cell] = acc.y;
                s_t[(lane * 4 + 2) * 49 + cell] = acc.z;
                s_t[(lane * 4 + 3) * 49 + cell] = acc.w;
            }
        } else {
            const float* plane = (lvl == 1) ? g_nhwc1 : g_nhwc2;
            const int W_ = (lvl == 1) ? W1 : W2;
            const int rNy = s_rN[1];
            const int rNx = s_rN[0];
            switch (rNy) {
                case 1: dispatch_rx<1>(rNx, plane, W_, chunk, s_cw, s_cb, wid, lane, s_t); break;
                case 2: dispatch_rx<2>(rNx, plane, W_, chunk, s_cw, s_cb, wid, lane, s_t); break;
                case 3: dispatch_rx<3>(rNx, plane, W_, chunk, s_cw, s_cb, wid, lane, s_t); break;
                case 4: dispatch_rx<4>(rNx, plane, W_, chunk, s_cw, s_cb, wid, lane, s_t); break;
                default: dispatch_rx<5>(rNx, plane, W_, chunk, s_cw, s_cb, wid, lane, s_t); break;
            }
        }
        __syncthreads();
        // write 128 channel rows (49 contiguous floats each) to NCHW output
        for (int r = wid; r < 128; r += 8) {
            float* drow = outd + (chunk * 128 + r) * 49;
            drow[lane] = s_t[r * 49 + lane];
            if (lane < 17) drow[32 + lane] = s_t[r * 49 + 32 + lane];
        }
        __syncthreads();
    }
}

extern "C" void kernel_launch(void* const* d_in, const int* in_sizes, int n_in,
                              void* d_out, int out_size) {
    const float* feat0 = (const float*)d_in[0];
    const float* feat1 = (const float*)d_in[1];
    const float* feat2 = (const float*)d_in[2];
    const float* boxes = (const float*)d_in[3];
    float* out = (float*)d_out;

    dim3 tb(32, 8);
    transpose_all_kernel<<<dim3(NB0 + NB1 + NB2, 8), tb>>>(feat0, feat1, feat2);

    roialign_nhwc_kernel<<<dim3(NBOX, 3), 256>>>(boxes, out);
}